// round 6
// baseline (speedup 1.0000x reference)
#include <cuda_runtime.h>
#include <cstdint>

// TaylorExp, one row per warp, phase-aligned body.
// out[m] for m>=1: p[(m-1)>>4] * q[(m-1)&15], p[0]=1, p[1+i]=2*s_quad*x[i],
// q[j]=x[j]/2 (s_quad = 1/(sqrt(2)*sqrt(16))). out[0]=1.
//   m=1..16  -> p[0]*q[m-1]      = x[m-1]*0.5            (linear)
//   m=17+k   -> p[1+(k>>4)]*q[k&15] = s_quad*x_i*x_j     (quadratic)
//
// Row r (base r*273 === r mod 4): head of H = 4-(r&3) scalars, then
// Nb = (273-H)/4 aligned float4 stores, then T = (273-H)&3 scalar tail.
// Body: m = H + 4*(lane + 32*s). 128 === 0 (mod 16) => b0=(m-1)&15, the
// wrap-select predicates and the q4 pointer are sweep-INVARIANT;
// a0=(m-1)>>4 advances by +8 per sweep. No row crossings.

#define D 16
#define OPR 273
#define THREADS 256
#define WARPS 8
#define ROW_STRIDE 40   // floats per row in smem (160B, 16B multiple)

__global__ __launch_bounds__(THREADS)
void taylor_rowwarp_kernel(const float* __restrict__ x,
                           float* __restrict__ out,
                           int rows)
{
    __shared__ __align__(16) float s[WARPS * ROW_STRIDE];

    const int tid = threadIdx.x;
    const int row0 = blockIdx.x * WARPS;

    if (row0 + WARPS <= rows) {
        // ---- stage p/q for 8 rows (coalesced 512B x load) ----
        if (tid < WARPS * D) {
            const int rl = tid >> 4;
            const int j  = tid & 15;
            const float v = x[(size_t)(row0 + rl) * D + j];
            const int rb = rl * ROW_STRIDE;
            const int qs = rb + 17 + ((row0 + rl) & 3);
            s[rb + 1 + j] = v * 0.35355339059327378f;  // p[1+j] = 2*s_quad*x[j]
            s[qs + j]     = v * 0.5f;                  // q[j]   = x[j]/2
            if (j < 3) s[qs + 16 + j] = v * 0.5f;      // wrap replicas q[16..18]
            if (j == 0) s[rb] = 1.0f;                  // p[0]
        }
        __syncthreads();

        const int warp = tid >> 5;
        const int lane = tid & 31;
        const int r  = row0 + warp;
        const int r3 = r & 3;
        const int H  = 4 - r3;                          // head length 1..4

        const float* __restrict__ sp = s + warp * ROW_STRIDE;       // p[0..16]
        const float* __restrict__ sq = sp + 17 + r3;                // q_ext[0..18]

        float* __restrict__ ob = out + (size_t)r * OPR;

        // ---- head: m = 0..H-1 (all linear/constant region) ----
        if (lane < H) {
            ob[lane] = (lane == 0) ? 1.0f : sq[lane - 1];
        }

        // ---- body: Nb aligned float4 stores ----
        const int Nb = (OPR - H) >> 2;                  // 67 or 68
        const int m0 = H + 4 * lane;
        const int t0 = m0 - 1;
        const int b0 = t0 & 15;                         // sweep-invariant
        int a0 = t0 >> 4;

        // (17 + r3 + b0) === 0 (mod 4)  =>  16B-aligned smem v4 load
        const float4 q4 = *reinterpret_cast<const float4*>(sq + b0);
        const bool w1 = (b0 + 1) >= 16;                 // hoisted wrap selects
        const bool w2 = (b0 + 2) >= 16;
        const bool w3 = (b0 + 3) >= 16;

        const float* pp = sp + a0;
        float4* __restrict__ op = reinterpret_cast<float4*>(ob + m0);

        #pragma unroll
        for (int sw = 0; sw < 3; ++sw) {
            if (lane + 32 * sw < Nb) {
                const float plo = pp[0];
                const float phi = pp[1];                // in-bounds pad; unused if a0==16
                float4 v;
                v.x = plo * q4.x;
                v.y = (w1 ? phi : plo) * q4.y;
                v.z = (w2 ? phi : plo) * q4.z;
                v.w = (w3 ? phi : plo) * q4.w;
                op[32 * sw] = v;
            }
            pp += 8;                                    // a0 += 8 per sweep
        }

        // ---- tail: T = (273-H)&3 scalars ----
        const int T = (OPR - H) & 3;
        if (lane < T) {
            const int m = H + 4 * Nb + lane;
            const int t = m - 1;
            ob[m] = sp[t >> 4] * sq[t & 15];
        }
    } else {
        // partial tail block (not hit for the bench shape): scalar fallback
        const float s_quad = 0.17677669529663689f;
        const unsigned int iend = (unsigned int)rows * OPR;
        for (unsigned int g = (unsigned int)row0 * OPR + tid; g < iend;
             g += THREADS) {
            const unsigned int row = g / OPR;
            const int mm = (int)(g - row * OPR);
            const float* xr = x + (size_t)row * D;
            float v;
            if (mm == 0) v = 1.0f;
            else if (mm < 17) v = xr[mm - 1] * 0.5f;
            else { const int k = mm - 17; v = xr[k >> 4] * xr[k & 15] * s_quad; }
            out[g] = v;
        }
    }
}

extern "C" void kernel_launch(void* const* d_in, const int* in_sizes, int n_in,
                              void* d_out, int out_size) {
    const float* x = (const float*)d_in[0];
    float* out = (float*)d_out;

    const int rows = in_sizes[0] / D;                   // 262144
    const int blocks = (rows + WARPS - 1) / WARPS;      // 32768

    taylor_rowwarp_kernel<<<blocks, THREADS>>>(x, out, rows);
}

// round 7
// speedup vs baseline: 1.1618x; 1.1618x over previous
#include <cuda_runtime.h>
#include <cstdint>

// TaylorExp, 4 rows per warp, fully unrolled sweeps with compile-time
// crossing positions.
// Per row: p[0]=1, p[1+i]=2*s_quad*x[i]; q_ext[j]=x[j mod 16]/2 (j=0..18).
// out[m] = p[t>>4]*q[t&15], t=m-1 (m>=1); out[0]=1.
// Group of 4 rows = 1092 floats = 273 float4 stores (group base 16B-aligned),
// 9 warp sweeps (last: 17 lanes). Row crossings are at fixed (sweep,lane):
// f4#0=(s0,l0), #68=(s2,l4), #136=(s4,l8), #204=(s6,l12) -> tiny fixups.
// Per-row q pad of rl words keeps every LDS.128 16B-aligned
// (C_s === -(rl+1) mod 4 for row rl).

#define D 16
#define OPR 273
#define THREADS 256
#define ROWS_PER_BLOCK 32
#define RS 40   // smem words per row: p[17], pad(rl), q_ext[19]

__global__ __launch_bounds__(THREADS)
void taylor_u9_kernel(const float* __restrict__ x,
                      float* __restrict__ out,
                      int rows)
{
    __shared__ __align__(16) float sm[ROWS_PER_BLOCK * RS];

    const int tid = threadIdx.x;
    const int row0 = blockIdx.x * ROWS_PER_BLOCK;

    if (row0 + ROWS_PER_BLOCK <= rows) {
        // ---- stage p/q: 128 threads, one float4 of x each (coalesced) ----
        if (tid < 128) {
            const int lr = tid >> 2;               // local row 0..31
            const int jb = (tid & 3) << 2;         // j base 0,4,8,12
            const float4 f = *reinterpret_cast<const float4*>(
                x + (size_t)(row0 + lr) * D + jb);
            const int rb = lr * RS;
            const int qb = rb + 17 + (lr & 3);     // q pad = rl
            const float ps = 0.35355339059327378f; // 2*s_quad
            sm[rb + 1 + jb] = f.x * ps;
            sm[rb + 2 + jb] = f.y * ps;
            sm[rb + 3 + jb] = f.z * ps;
            sm[rb + 4 + jb] = f.w * ps;
            sm[qb + jb + 0] = f.x * 0.5f;
            sm[qb + jb + 1] = f.y * 0.5f;
            sm[qb + jb + 2] = f.z * 0.5f;
            sm[qb + jb + 3] = f.w * 0.5f;
            if (jb == 0) {
                sm[rb] = 1.0f;                     // p[0]
                sm[qb + 16] = f.x * 0.5f;          // wrap replicas q[16..18]
                sm[qb + 17] = f.y * 0.5f;
                sm[qb + 18] = f.z * 0.5f;
            }
        }
        __syncthreads();

        const int warp = tid >> 5;
        const int lane = tid & 31;
        const int l4 = lane << 2;
        const int wb = warp * (4 * RS);

        // compile-time-per-sweep row offsets (words)
        const int P0 = wb,       Q0 = wb + 17;        // pad 0
        const int P1 = wb + 40,  Q1 = wb + 40 + 18;   // pad 1
        const int P2 = wb + 80,  Q2 = wb + 80 + 19;   // pad 2
        const int P3 = wb + 120, Q3 = wb + 120 + 20;  // pad 3

        float4* __restrict__ ob = reinterpret_cast<float4*>(
            out + (size_t)(row0 + warp * 4) * OPR) + lane;

        // BODY: v[k] = p[(t0+k)>>4] * q[(t0+k)&15] via plo/phi + wrap selects.
        // AM==1 clamps a0 for the lane-0/sweep-0 t0=-1 case (b0=15 stays aligned).
#define BODY(P, Q, T0, V, AM)                                               \
        {                                                                   \
            const int t0_ = (T0);                                           \
            const int b0_ = t0_ & 15;                                       \
            const int a0_ = (AM ? (t0_ < 0 ? 0 : t0_) : t0_) >> 4;          \
            const float plo_ = sm[(P) + a0_];                               \
            const float phi_ = sm[(P) + a0_ + 1];                           \
            const float4 q4_ =                                              \
                *reinterpret_cast<const float4*>(&sm[(Q) + b0_]);           \
            V.x = plo_ * q4_.x;                                             \
            V.y = (b0_ >= 15 ? phi_ : plo_) * q4_.y;                        \
            V.z = (b0_ >= 14 ? phi_ : plo_) * q4_.z;                        \
            V.w = (b0_ >= 13 ? phi_ : plo_) * q4_.w;                        \
        }

        float4 v;

        // s=0: row0, C=-1. lane0 covers out[0..3] -> fixup.
        BODY(P0, Q0, l4 - 1, v, 1);
        if (lane == 0) { v.x = 1.0f; v.y = sm[Q0]; v.z = sm[Q0 + 1]; v.w = sm[Q0 + 2]; }
        ob[0] = v;

        // s=1: row0, C=127.
        BODY(P0, Q0, l4 + 127, v, 0);
        ob[32] = v;

        // s=2: lanes<=4 row0 (C=255), lanes>=5 row1 (C=-18). lane4 mixed.
        {
            const bool hi = lane >= 5;
            BODY(hi ? P1 : P0, hi ? Q1 : Q0, l4 + (hi ? -18 : 255), v, 0);
            if (lane == 4) { v.y = 1.0f; v.z = sm[Q1]; v.w = sm[Q1 + 1]; }
            ob[64] = v;
        }

        // s=3: row1, C=110.
        BODY(P1, Q1, l4 + 110, v, 0);
        ob[96] = v;

        // s=4: lanes<=8 row1 (C=238), lanes>=9 row2 (C=-35). lane8 mixed.
        {
            const bool hi = lane >= 9;
            BODY(hi ? P2 : P1, hi ? Q2 : Q1, l4 + (hi ? -35 : 238), v, 0);
            if (lane == 8) { v.z = 1.0f; v.w = sm[Q2]; }
            ob[128] = v;
        }

        // s=5: row2, C=93.
        BODY(P2, Q2, l4 + 93, v, 0);
        ob[160] = v;

        // s=6: lanes<=12 row2 (C=221), lanes>=13 row3 (C=-52). lane12 mixed.
        {
            const bool hi = lane >= 13;
            BODY(hi ? P3 : P2, hi ? Q3 : Q2, l4 + (hi ? -52 : 221), v, 0);
            if (lane == 12) { v.w = 1.0f; }
            ob[192] = v;
        }

        // s=7: row3, C=76.
        BODY(P3, Q3, l4 + 76, v, 0);
        ob[224] = v;

        // s=8: row3, C=204, lanes 0..16 only.
        if (lane < 17) {
            BODY(P3, Q3, l4 + 204, v, 0);
            ob[256] = v;
        }
#undef BODY
    } else {
        // partial tail block (not hit for the bench shape): scalar fallback
        const float s_quad = 0.17677669529663689f;
        const unsigned int iend = (unsigned int)rows * OPR;
        for (unsigned int g = (unsigned int)row0 * OPR + tid; g < iend;
             g += THREADS) {
            const unsigned int row = g / OPR;
            const int mm = (int)(g - row * OPR);
            const float* xr = x + (size_t)row * D;
            float vv;
            if (mm == 0) vv = 1.0f;
            else if (mm < 17) vv = xr[mm - 1] * 0.5f;
            else { const int k = mm - 17; vv = xr[k >> 4] * xr[k & 15] * s_quad; }
            out[g] = vv;
        }
    }
}

extern "C" void kernel_launch(void* const* d_in, const int* in_sizes, int n_in,
                              void* d_out, int out_size) {
    const float* x = (const float*)d_in[0];
    float* out = (float*)d_out;

    const int rows = in_sizes[0] / D;                        // 262144
    const int blocks = (rows + ROWS_PER_BLOCK - 1) / ROWS_PER_BLOCK; // 8192

    taylor_u9_kernel<<<blocks, THREADS>>>(x, out, rows);
}